// round 1
// baseline (speedup 1.0000x reference)
#include <cuda_runtime.h>
#include <cstdint>

// AnchorLoss: sum over masked pairs of 1 - exp(-||p_i - p_j||^2 / 10),
// p = embedding + abs_coords, B=8, N=2048, D=2.

constexpr int BDIM = 8;
constexpr int NDIM = 2048;
constexpr int ROWS = 8;            // i-rows per block (one warp per row)
constexpr int THREADS = ROWS * 32; // 256
constexpr int GRID_X = NDIM / ROWS;       // 256
constexpr int NBLOCKS = GRID_X * BDIM;    // 2048
constexpr int Q = NDIM / 4;               // 512 (transposed stride)

__device__ float g_partial[NBLOCKS];

__device__ __forceinline__ float ex2_approx(float x) {
    float r;
    asm("ex2.approx.ftz.f32 %0, %1;" : "=f"(r) : "f"(x));
    return r;
}

__global__ void __launch_bounds__(THREADS, 8)
anchor_main(const float* __restrict__ emb,
            const float* __restrict__ coords,
            const int*   __restrict__ mask) {
    // Transposed point cache: sp[(j&3)*Q + (j>>2)] = p[j]
    __shared__ float2 sp[NDIM];
    __shared__ float wsum[ROWS];

    const int b = blockIdx.y;
    const float2* e2 = reinterpret_cast<const float2*>(emb    + (size_t)b * NDIM * 2);
    const float2* c2 = reinterpret_cast<const float2*>(coords + (size_t)b * NDIM * 2);
    for (int t = threadIdx.x; t < NDIM; t += THREADS) {
        float2 e = e2[t];
        float2 c = c2[t];
        sp[(t & 3) * Q + (t >> 2)] = make_float2(e.x + c.x, e.y + c.y);
    }
    __syncthreads();

    const int warp = threadIdx.x >> 5;
    const int lane = threadIdx.x & 31;
    const int i = blockIdx.x * ROWS + warp;

    const float2 pi = sp[(i & 3) * Q + (i >> 2)];
    const int4* mrow = reinterpret_cast<const int4*>(
        mask + ((size_t)b * NDIM + (size_t)i) * NDIM);

    constexpr float NEGC = -0.14426950408889634f;  // -log2(e)/TEMPERATURE

    float accE = 0.0f;  // sum of m * exp(...)
    int   cnt  = 0;     // count of m==1

#pragma unroll 4
    for (int it = 0; it < NDIM / 128; ++it) {  // 16 iterations
        const int a = it * 32 + lane;          // int4 index == transposed index
        const int4 m = __ldcs(&mrow[a]);       // masks for j = 4a .. 4a+3

        const float2 p0 = sp[0 * Q + a];
        const float2 p1 = sp[1 * Q + a];
        const float2 p2 = sp[2 * Q + a];
        const float2 p3 = sp[3 * Q + a];

        {
            float dx = pi.x - p0.x, dy = pi.y - p0.y;
            float arg = fmaf(dy, dy, dx * dx) * NEGC;
            accE = fmaf((float)m.x, ex2_approx(arg), accE);
            cnt += m.x;
        }
        {
            float dx = pi.x - p1.x, dy = pi.y - p1.y;
            float arg = fmaf(dy, dy, dx * dx) * NEGC;
            accE = fmaf((float)m.y, ex2_approx(arg), accE);
            cnt += m.y;
        }
        {
            float dx = pi.x - p2.x, dy = pi.y - p2.y;
            float arg = fmaf(dy, dy, dx * dx) * NEGC;
            accE = fmaf((float)m.z, ex2_approx(arg), accE);
            cnt += m.z;
        }
        {
            float dx = pi.x - p3.x, dy = pi.y - p3.y;
            float arg = fmaf(dy, dy, dx * dx) * NEGC;
            accE = fmaf((float)m.w, ex2_approx(arg), accE);
            cnt += m.w;
        }
    }

    float val = (float)cnt - accE;

    // warp reduce
#pragma unroll
    for (int off = 16; off; off >>= 1)
        val += __shfl_xor_sync(0xffffffffu, val, off);

    if (lane == 0) wsum[warp] = val;
    __syncthreads();

    if (threadIdx.x == 0) {
        float s = 0.0f;
#pragma unroll
        for (int w = 0; w < ROWS; ++w) s += wsum[w];
        g_partial[blockIdx.y * GRID_X + blockIdx.x] = s;
    }
}

__global__ void __launch_bounds__(256)
anchor_reduce(float* __restrict__ out) {
    __shared__ double s[256];
    double acc = 0.0;
    for (int idx = threadIdx.x; idx < NBLOCKS; idx += 256)
        acc += (double)g_partial[idx];
    s[threadIdx.x] = acc;
    __syncthreads();
#pragma unroll
    for (int off = 128; off; off >>= 1) {
        if (threadIdx.x < off) s[threadIdx.x] += s[threadIdx.x + off];
        __syncthreads();
    }
    if (threadIdx.x == 0) out[0] = (float)s[0];
}

extern "C" void kernel_launch(void* const* d_in, const int* in_sizes, int n_in,
                              void* d_out, int out_size) {
    const float* emb    = (const float*)d_in[0];
    const float* coords = (const float*)d_in[1];
    const int*   mask   = (const int*)d_in[2];
    float* out = (float*)d_out;

    dim3 grid(GRID_X, BDIM);
    anchor_main<<<grid, THREADS>>>(emb, coords, mask);
    anchor_reduce<<<1, 256>>>(out);
}